// round 4
// baseline (speedup 1.0000x reference)
#include <cuda_runtime.h>
#include <cuda_bf16.h>
#include <cstdint>

#define NC   81
#define NCP  96
#define BK   10
#define DIM  2048
#define NI   16384
#define NT   64          /* k-tiles of 32 fp32 dims */
#define BMG  128         /* gemm instances per block */

__device__ int   g_count;
__device__ int   g_nfix;
__device__ int   g_fix[NI];
__device__ float g_bias[NCP];
__device__ float g_mmean[NC * DIM];
// [tile][class][hi(32)|lo(32)] bf16 => 128B per class-row per tile
__device__ __align__(16) unsigned short g_mbf[NT * NCP * 64];

__device__ __forceinline__ uint32_t smem_u32(const void* p) {
    uint32_t a;
    asm("{ .reg .u64 t; cvta.to.shared.u64 t, %1; cvt.u32.u64 %0, t; }" : "=r"(a) : "l"(p));
    return a;
}

#define LDSM_X4(r0, r1, r2, r3, addr)                                         \
    asm volatile("ldmatrix.sync.aligned.m8n8.x4.shared.b16 {%0,%1,%2,%3}, [%4];" \
                 : "=r"(r0), "=r"(r1), "=r"(r2), "=r"(r3) : "r"(addr))

#define MMA16816(d, a, b0v, b1v)                                              \
    asm volatile("mma.sync.aligned.m16n8k16.row.col.f32.bf16.bf16.f32 "       \
                 "{%0,%1,%2,%3},{%4,%5,%6,%7},{%8,%9},{%0,%1,%2,%3};"         \
                 : "+f"((d)[0]), "+f"((d)[1]), "+f"((d)[2]), "+f"((d)[3])     \
                 : "r"((a)[0]), "r"((a)[1]), "r"((a)[2]), "r"((a)[3]),        \
                   "r"(b0v), "r"(b1v))

#define FMA2(d, a, b, c) asm("fma.rn.f32x2 %0, %1, %2, %3;" : "=l"(d) : "l"(a), "l"(b), "l"(c))
#define ADD2(d, a, b)    asm("add.rn.f32x2 %0, %1, %2;" : "=l"(d) : "l"(a), "l"(b))
#define UNPACK2(lo, hi, v) asm("mov.b64 {%0, %1}, %2;" : "=f"(lo), "=f"(hi) : "l"(v))

__device__ __forceinline__ unsigned pkbf(__nv_bfloat16 a, __nv_bfloat16 b) {
    return ((unsigned)__bfloat16_as_ushort(b) << 16) | (unsigned)__bfloat16_as_ushort(a);
}

// ---------------------------------------------------------------------------
// Kernel 1: class means -> fp32 plane + bf16 hi/lo planes + bias; zero pads.
// ---------------------------------------------------------------------------
__global__ void k_mean(const float* __restrict__ mem) {
    int c = blockIdx.x, tid = threadIdx.x;
    if (c == 0 && tid == 0) { g_count = 0; g_nfix = 0; }
    if (c >= NC) {
        for (int d = tid; d < DIM; d += 256) {
            int tt = d >> 5, j = d & 31;
            g_mbf[(tt * NCP + c) * 64 + j] = 0;
            g_mbf[(tt * NCP + c) * 64 + 32 + j] = 0;
        }
        return;
    }
    float part = 0.f;
    for (int d = tid; d < DIM; d += 256) {
        float s = 0.f;
#pragma unroll
        for (int b = 0; b < BK; b++) s += mem[(size_t)(c * BK + b) * DIM + d];
        float m = s * (1.0f / BK);
        g_mmean[c * DIM + d] = m;
        __nv_bfloat16 hi = __float2bfloat16_rn(m);
        __nv_bfloat16 lo = __float2bfloat16_rn(m - __bfloat162float(hi));
        int tt = d >> 5, j = d & 31;
        g_mbf[(tt * NCP + c) * 64 + j] = __bfloat16_as_ushort(hi);
        g_mbf[(tt * NCP + c) * 64 + 32 + j] = __bfloat16_as_ushort(lo);
        part += m * m;
    }
#pragma unroll
    for (int o = 16; o; o >>= 1) part += __shfl_xor_sync(0xffffffffu, part, o);
    __shared__ float rb[8];
    if ((tid & 31) == 0) rb[tid >> 5] = part;
    __syncthreads();
    if (tid == 0) {
        float t = 0.f;
#pragma unroll
        for (int w = 0; w < 8; w++) t += rb[w];
        g_bias[c] = 0.5f * t;
    }
}

// ---------------------------------------------------------------------------
// Kernel 2: HMMA bf16-split GEMM + argmin + near-tie fixup list.
// 128 inst x 96 cls per block. Smem: double-buffered stage of
// A(128x128B SW128) + B(96x128B SW128) = 28672B each. Row = [hi 64B | lo 64B].
// 8 warps = 4 Mwarps x 2 Nwarps; warp tile 32x48 (2 m16 x 6 n8).
// ---------------------------------------------------------------------------
#define STAGE 28672
#define SMEM_GEMM (2 * STAGE)
__global__ void __launch_bounds__(256, 1)
k_gemm(const float* __restrict__ X, const int* __restrict__ labels,
       float* __restrict__ out) {
    extern __shared__ char sm[];
    const uint32_t sb = smem_u32(sm);
    const int tid = threadIdx.x, wid = tid >> 5, lane = tid & 31;
    const int i0 = blockIdx.x * BMG;
    const int mwarp = wid & 3, nwarp = wid >> 2;

    const int r = tid >> 1, h = tid & 1;
    const float* xrow = X + (size_t)(i0 + r) * DIM + h * 16;
    const uint4* mb4 = (const uint4*)g_mbf;

    float d[2][6][4];
#pragma unroll
    for (int a = 0; a < 2; a++)
#pragma unroll
        for (int b = 0; b < 6; b++)
#pragma unroll
            for (int e = 0; e < 4; e++) d[a][b][e] = 0.f;

    float4 cur0, cur1, cur2, cur3;
#define GLOAD(t)                                                    \
    {   const float4* p4 = (const float4*)(xrow + (t) * 32);        \
        cur0 = p4[0]; cur1 = p4[1]; cur2 = p4[2]; cur3 = p4[3]; }

// convert 16 fp32 -> hi/lo bf16, store swizzled; plus copy B tile
#define GSTORE(t, buf)                                                          \
    {   float f[16];                                                            \
        *(float4*)(f + 0) = cur0; *(float4*)(f + 4) = cur1;                     \
        *(float4*)(f + 8) = cur2; *(float4*)(f + 12) = cur3;                    \
        unsigned hw[8], lw[8];                                                  \
        _Pragma("unroll") for (int j = 0; j < 8; j++) {                         \
            float x0 = f[2 * j], x1 = f[2 * j + 1];                             \
            __nv_bfloat16 h0 = __float2bfloat16_rn(x0);                         \
            __nv_bfloat16 h1 = __float2bfloat16_rn(x1);                         \
            __nv_bfloat16 l0 = __float2bfloat16_rn(x0 - __bfloat162float(h0));  \
            __nv_bfloat16 l1 = __float2bfloat16_rn(x1 - __bfloat162float(h1));  \
            hw[j] = pkbf(h0, h1); lw[j] = pkbf(l0, l1);                         \
        }                                                                       \
        char* Ab = sm + (buf) * STAGE;                                          \
        const int rx = r & 7;                                                   \
        *(uint4*)(Ab + r * 128 + 16 * ((2 * h + 0) ^ rx)) = make_uint4(hw[0], hw[1], hw[2], hw[3]); \
        *(uint4*)(Ab + r * 128 + 16 * ((2 * h + 1) ^ rx)) = make_uint4(hw[4], hw[5], hw[6], hw[7]); \
        *(uint4*)(Ab + r * 128 + 16 * ((4 + 2 * h) ^ rx)) = make_uint4(lw[0], lw[1], lw[2], lw[3]); \
        *(uint4*)(Ab + r * 128 + 16 * ((5 + 2 * h) ^ rx)) = make_uint4(lw[4], lw[5], lw[6], lw[7]); \
        char* Bb = Ab + 16384;                                                  \
        _Pragma("unroll") for (int q = 0; q < 3; q++) {                         \
            int g = tid + q * 256;                                              \
            int brow = g >> 3, bch = g & 7;                                     \
            *(uint4*)(Bb + brow * 128 + 16 * (bch ^ (brow & 7))) = mb4[(t) * 768 + g]; \
        }                                                                       \
    }

    GLOAD(0);
    GSTORE(0, 0);

    for (int t = 0; t < NT; t++) {
        const int buf = t & 1;
        if (t + 1 < NT) GLOAD(t + 1);
        __syncthreads();

        const uint32_t Abase = sb + buf * STAGE;
        const uint32_t Bbase = Abase + 16384;

        // A fragments: [mt][plane][s][4]
        uint32_t afr[2][2][2][4];
#pragma unroll
        for (int mt = 0; mt < 2; mt++) {
            int rowA = mwarp * 32 + mt * 16 + (lane & 15);
            uint32_t rbase = Abase + rowA * 128;
            int rx = rowA & 7;
#pragma unroll
            for (int pl = 0; pl < 2; pl++)
#pragma unroll
                for (int s = 0; s < 2; s++) {
                    int ch = pl * 4 + s * 2 + (lane >> 4);
                    uint32_t ad = rbase + 16 * (ch ^ rx);
                    LDSM_X4(afr[mt][pl][s][0], afr[mt][pl][s][1],
                            afr[mt][pl][s][2], afr[mt][pl][s][3], ad);
                }
        }

#pragma unroll
        for (int pp = 0; pp < 3; pp++) {
            const int apl = (pp == 2) ? 1 : 0;
            const int bpl = (pp == 1) ? 1 : 0;
#pragma unroll
            for (int np = 0; np < 3; np++) {
                int rowB = nwarp * 48 + np * 16 + (lane & 15);
                uint32_t rbase = Bbase + rowB * 128;
                int rx = rowB & 7;
#pragma unroll
                for (int s = 0; s < 2; s++) {
                    int ch = bpl * 4 + s * 2 + (lane >> 4);
                    uint32_t bd = rbase + 16 * (ch ^ rx);
                    uint32_t b0, b1, b2, b3;
                    LDSM_X4(b0, b1, b2, b3, bd);
#pragma unroll
                    for (int mt = 0; mt < 2; mt++) {
                        MMA16816(d[mt][np * 2 + 0], afr[mt][apl][s], b0, b2);
                        MMA16816(d[mt][np * 2 + 1], afr[mt][apl][s], b1, b3);
                    }
                }
            }
        }
        __syncthreads();
        if (t + 1 < NT) GSTORE(t + 1, (t + 1) & 1);
    }
    __syncthreads();

    // epilogue: scores -> smem [row][col], stride 97
    float* sc = (float*)sm;
#pragma unroll
    for (int mt = 0; mt < 2; mt++) {
#pragma unroll
        for (int np = 0; np < 3; np++)
#pragma unroll
            for (int hh = 0; hh < 2; hh++) {
                int row0 = mwarp * 32 + mt * 16 + (lane >> 2);
                int col0 = nwarp * 48 + np * 16 + hh * 8 + 2 * (lane & 3);
                const float* dd = d[mt][np * 2 + hh];
                if (col0 < NC) sc[row0 * 97 + col0] = g_bias[col0] - dd[0];
                if (col0 + 1 < NC) sc[row0 * 97 + col0 + 1] = g_bias[col0 + 1] - dd[1];
                if (col0 < NC) sc[(row0 + 8) * 97 + col0] = g_bias[col0] - dd[2];
                if (col0 + 1 < NC) sc[(row0 + 8) * 97 + col0 + 1] = g_bias[col0 + 1] - dd[3];
            }
    }
    __syncthreads();

    if (tid < BMG) {
        int gi = i0 + tid;
        const float* row = sc + tid * 97;
        float best = 3e38f, sec = 3e38f;
        int bc = 0;
#pragma unroll 4
        for (int cc = 0; cc < NC; cc++) {
            float v = row[cc];
            if (v < best) { sec = best; best = v; bc = cc; }
            else if (v < sec) sec = v;
        }
        out[gi] = (float)bc;
        if (sec - best < 0.02f) {
            int slot = atomicAdd(&g_nfix, 1);
            if (slot < NI) g_fix[slot] = gi;
        }
        unsigned bal = __ballot_sync(0xffffffffu, bc == labels[gi]);
        if ((tid & 31) == 0) atomicAdd(&g_count, __popc(bal));
    }
}

// ---------------------------------------------------------------------------
// Kernel 2b: exact fp32 re-check of near-tie instances; patch out + g_count.
// ---------------------------------------------------------------------------
__global__ void __launch_bounds__(256) k_fixup(const float* __restrict__ X,
                                               const int* __restrict__ labels,
                                               float* __restrict__ out) {
    const int tid = threadIdx.x, w = tid >> 5, lane = tid & 31;
    __shared__ float ssc[NC];
    const int nfix = g_nfix < NI ? g_nfix : NI;
    for (int idx = blockIdx.x; idx < nfix; idx += gridDim.x) {
        const int gi = g_fix[idx];
        const float4* x4 = (const float4*)(X + (size_t)gi * DIM);
        for (int c = w; c < NC; c += 8) {
            const float4* m4 = (const float4*)(g_mmean + (size_t)c * DIM);
            float s = 0.f;
#pragma unroll
            for (int k = 0; k < 16; k++) {
                float4 a = x4[k * 32 + lane];
                float4 b = m4[k * 32 + lane];
                s += a.x * b.x + a.y * b.y + a.z * b.z + a.w * b.w;
            }
#pragma unroll
            for (int o = 16; o; o >>= 1) s += __shfl_xor_sync(0xffffffffu, s, o);
            if (lane == 0) ssc[c] = g_bias[c] - s;
        }
        __syncthreads();
        if (tid == 0) {
            float best = 3e38f;
            int bc = 0;
            for (int cc = 0; cc < NC; cc++) {
                float v = ssc[cc];
                if (v < best) { best = v; bc = cc; }
            }
            int oldbc = (int)out[gi];
            if (oldbc != bc) {
                int lab = labels[gi];
                atomicAdd(&g_count, (bc == lab) - (oldbc == lab));
                out[gi] = (float)bc;
            }
        }
        __syncthreads();
    }
}

// ---------------------------------------------------------------------------
// Kernel 3: sequential per-class memory update (one block/class), prefetch-2.
// Also finalizes accuracy.
// ---------------------------------------------------------------------------
__global__ void __launch_bounds__(256, 1)
k_update(const float* __restrict__ X, const int* __restrict__ labels,
         const float* __restrict__ mem, const int* __restrict__ mpos,
         float* __restrict__ out) {
    const int c = blockIdx.x, tid = threadIdx.x;
    const int w = tid >> 5, lane = tid & 31;
    if (c == 0 && tid == 0) out[NI] = (float)g_count * (1.0f / NI);

    __shared__ int   s_list[1024];
    __shared__ int   s_cnt;
    __shared__ int   s_wcnt[8];
    __shared__ float s_part[2][8][12];

    const int SEG = NI / 8;
    const int base = w * SEG;
    const int4* lab4 = (const int4*)labels;
    int cnt = 0;
    for (int it = 0; it < SEG / 128; it++) {
        int4 v = lab4[(base >> 2) + it * 32 + lane];
        cnt += (v.x == c) + (v.y == c) + (v.z == c) + (v.w == c);
    }
#pragma unroll
    for (int o = 16; o; o >>= 1) cnt += __shfl_xor_sync(0xffffffffu, cnt, o);
    if (lane == 0) s_wcnt[w] = cnt;
    __syncthreads();
    if (tid == 0) {
        int t = 0;
        for (int ww = 0; ww < 8; ww++) { int v = s_wcnt[ww]; s_wcnt[ww] = t; t += v; }
        s_cnt = t;
    }
    __syncthreads();
    int off = s_wcnt[w];
    for (int it = 0; it < SEG / 128; it++) {
        int gidx = base + it * 128 + lane * 4;
        int4 v = lab4[gidx >> 2];
        int m0 = (v.x == c), m1 = (v.y == c), m2 = (v.z == c), m3 = (v.w == c);
        int nm = m0 + m1 + m2 + m3;
        int x = nm;
#pragma unroll
        for (int o = 1; o < 32; o <<= 1) {
            int y = __shfl_up_sync(0xffffffffu, x, o);
            if (lane >= o) x += y;
        }
        int p2 = off + x - nm;
        if (m0) { s_list[p2 < 1024 ? p2 : 1023] = gidx + 0; p2++; }
        if (m1) { s_list[p2 < 1024 ? p2 : 1023] = gidx + 1; p2++; }
        if (m2) { s_list[p2 < 1024 ? p2 : 1023] = gidx + 2; p2++; }
        if (m3) { s_list[p2 < 1024 ? p2 : 1023] = gidx + 3; p2++; }
        off += __shfl_sync(0xffffffffu, x, 31);
    }
    __syncthreads();

    const ulonglong2* memU = (const ulonglong2*)mem + (size_t)c * BK * (DIM / 4);
    ulonglong2 br[BK][2];
    float part[11];
#pragma unroll
    for (int j = 0; j < BK; j++) {
        br[j][0] = memU[j * 512 + tid];
        br[j][1] = memU[j * 512 + 256 + tid];
        unsigned long long pa = 0ull;
        FMA2(pa, br[j][0].x, br[j][0].x, pa);
        FMA2(pa, br[j][0].y, br[j][0].y, pa);
        FMA2(pa, br[j][1].x, br[j][1].x, pa);
        FMA2(pa, br[j][1].y, br[j][1].y, pa);
        float lo, hi; UNPACK2(lo, hi, pa);
        part[j] = lo + hi;
    }
#pragma unroll
    for (int j = 0; j < BK; j++) {
        float v = part[j];
#pragma unroll
        for (int o = 16; o; o >>= 1) v += __shfl_xor_sync(0xffffffffu, v, o);
        part[j] = v;
    }
#pragma unroll
    for (int j = 0; j < BK; j++) if (lane == j) s_part[0][w][j] = part[j];
    if (lane == 10 || lane == 11) s_part[0][w][lane] = 0.f;
    __syncthreads();

    float bn[BK];
    {
        unsigned long long s0 = 0, s1 = 0, s2 = 0, s3 = 0, s4 = 0;
#pragma unroll
        for (int ww = 0; ww < 8; ww++) {
            const ulonglong2* rr = (const ulonglong2*)s_part[0][ww];
            ulonglong2 q0 = rr[0], q1 = rr[1], q2 = rr[2];
            ADD2(s0, s0, q0.x); ADD2(s1, s1, q0.y);
            ADD2(s2, s2, q1.x); ADD2(s3, s3, q1.y);
            ADD2(s4, s4, q2.x); (void)q2.y;
        }
        UNPACK2(bn[0], bn[1], s0); UNPACK2(bn[2], bn[3], s1);
        UNPACK2(bn[4], bn[5], s2); UNPACK2(bn[6], bn[7], s3);
        UNPACK2(bn[8], bn[9], s4);
    }

    int p = mpos[c];
    const int n = s_cnt < 1024 ? s_cnt : 1024;
    const ulonglong2* XU = (const ulonglong2*)X;
    ulonglong2 xc0, xc1, xn0, xn1, xm0, xm1;
    xc0.x = xc0.y = xc1.x = xc1.y = 0ull;
    xn0 = xc0; xn1 = xc1; xm0 = xc0; xm1 = xc1;
    if (n > 0) {
        size_t rr = (size_t)s_list[0] * 512;
        xc0 = XU[rr + tid]; xc1 = XU[rr + 256 + tid];
    }
    if (n > 1) {
        size_t rr = (size_t)s_list[1] * 512;
        xn0 = XU[rr + tid]; xn1 = XU[rr + 256 + tid];
    }
    int buf = 1;
    for (int s = 0; s < n; s++) {
        if (s + 2 < n) {
            size_t rr = (size_t)s_list[s + 2] * 512;
            xm0 = XU[rr + tid]; xm1 = XU[rr + 256 + tid];
        }
        float p10;
#pragma unroll
        for (int j = 0; j < BK; j++) {
            unsigned long long pa = 0ull;
            FMA2(pa, br[j][0].x, xc0.x, pa);
            FMA2(pa, br[j][0].y, xc0.y, pa);
            FMA2(pa, br[j][1].x, xc1.x, pa);
            FMA2(pa, br[j][1].y, xc1.y, pa);
            float lo, hi; UNPACK2(lo, hi, pa);
            part[j] = lo + hi;
        }
        {
            unsigned long long pa = 0ull;
            FMA2(pa, xc0.x, xc0.x, pa); FMA2(pa, xc0.y, xc0.y, pa);
            FMA2(pa, xc1.x, xc1.x, pa); FMA2(pa, xc1.y, xc1.y, pa);
            float lo, hi; UNPACK2(lo, hi, pa);
            p10 = lo + hi;
        }
#pragma unroll
        for (int j = 0; j < BK; j++) {
            float v = part[j];
#pragma unroll
            for (int o = 16; o; o >>= 1) v += __shfl_xor_sync(0xffffffffu, v, o);
            part[j] = v;
        }
#pragma unroll
        for (int o = 16; o; o >>= 1) p10 += __shfl_xor_sync(0xffffffffu, p10, o);
#pragma unroll
        for (int j = 0; j < BK; j++) if (lane == j) s_part[buf][w][j] = part[j];
        if (lane == 10) s_part[buf][w][10] = p10;
        if (lane == 11) s_part[buf][w][11] = 0.f;
        __syncthreads();

        float tot[12];
        {
            unsigned long long s0 = 0, s1 = 0, s2 = 0, s3 = 0, s4 = 0, s5 = 0;
#pragma unroll
            for (int ww = 0; ww < 8; ww++) {
                const ulonglong2* rr = (const ulonglong2*)s_part[buf][ww];
                ulonglong2 q0 = rr[0], q1 = rr[1], q2 = rr[2];
                ADD2(s0, s0, q0.x); ADD2(s1, s1, q0.y);
                ADD2(s2, s2, q1.x); ADD2(s3, s3, q1.y);
                ADD2(s4, s4, q2.x); ADD2(s5, s5, q2.y);
            }
            UNPACK2(tot[0], tot[1], s0); UNPACK2(tot[2], tot[3], s1);
            UNPACK2(tot[4], tot[5], s2); UNPACK2(tot[6], tot[7], s3);
            UNPACK2(tot[8], tot[9], s4); UNPACK2(tot[10], tot[11], s5);
        }
        float xx = tot[10];

        int slot;
        if (p < BK) {
            slot = p;
        } else {
            float dd[BK];
#pragma unroll
            for (int j = 0; j < BK; j++) dd[j] = fmaf(-2.f, tot[j], bn[j]);
            float mx = dd[0];
#pragma unroll
            for (int j = 1; j < BK; j++) mx = fmaxf(mx, dd[j]);
            slot = BK - 1;
#pragma unroll
            for (int j = BK - 1; j >= 0; j--) slot = (dd[j] == mx) ? j : slot;
        }
#pragma unroll
        for (int j = 0; j < BK; j++) {
            bool hh = (slot == j);
            br[j][0].x = hh ? xc0.x : br[j][0].x;
            br[j][0].y = hh ? xc0.y : br[j][0].y;
            br[j][1].x = hh ? xc1.x : br[j][1].x;
            br[j][1].y = hh ? xc1.y : br[j][1].y;
            bn[j] = hh ? xx : bn[j];
        }
        if (p < BK) p++;
        xc0 = xn0; xc1 = xn1;
        xn0 = xm0; xn1 = xm1;
        buf ^= 1;
    }

    float* om = out + (NI + 1) + (size_t)c * BK * DIM;
#pragma unroll
    for (int j = 0; j < BK; j++) {
        float f0, f1, f2, f3;
        UNPACK2(f0, f1, br[j][0].x); UNPACK2(f2, f3, br[j][0].y);
        int d0 = j * DIM + tid * 4;
        om[d0 + 0] = f0; om[d0 + 1] = f1; om[d0 + 2] = f2; om[d0 + 3] = f3;
        UNPACK2(f0, f1, br[j][1].x); UNPACK2(f2, f3, br[j][1].y);
        int d1 = j * DIM + 1024 + tid * 4;
        om[d1 + 0] = f0; om[d1 + 1] = f1; om[d1 + 2] = f2; om[d1 + 3] = f3;
    }
    if (tid == 0) out[(NI + 1) + (size_t)NC * BK * DIM + c] = (float)p;
}

// ---------------------------------------------------------------------------
extern "C" void kernel_launch(void* const* d_in, const int* in_sizes, int n_in,
                              void* d_out, int out_size) {
    const float* X      = (const float*)d_in[0];
    const int*   labels = (const int*)d_in[1];
    const float* mem    = (const float*)d_in[2];
    const int*   mpos   = (const int*)d_in[3];
    float* out = (float*)d_out;

    static bool init = false;
    if (!init) {
        init = true;
        cudaFuncSetAttribute(k_gemm, cudaFuncAttributeMaxDynamicSharedMemorySize, SMEM_GEMM);
    }

    k_mean<<<NCP, 256>>>(mem);
    k_gemm<<<NI / BMG, 256, SMEM_GEMM>>>(X, labels, out);
    k_fixup<<<296, 256>>>(X, labels, out);
    k_update<<<NC, 256>>>(X, labels, mem, mpos, out);
}

// round 5
// speedup vs baseline: 1.5005x; 1.5005x over previous
#include <cuda_runtime.h>
#include <cuda_bf16.h>
#include <math_constants.h>
#include <cstdint>

#define NC   81
#define NCP  96
#define BK   10
#define DIM  2048
#define NI   16384
#define NT   64          /* k-tiles of 32 fp32 dims */
#define BMG  128         /* gemm instances per block */

__device__ int   g_count;
__device__ int   g_nfix;
__device__ int   g_fix[NI];
__device__ float g_bias[NCP];
__device__ float g_mmean[NC * DIM];
// [tile][class][hi(32)|lo(32)] bf16 => 128B per class-row per tile
__device__ __align__(16) unsigned short g_mbf[NT * NCP * 64];

__device__ __forceinline__ uint32_t smem_u32(const void* p) {
    uint32_t a;
    asm("{ .reg .u64 t; cvta.to.shared.u64 t, %1; cvt.u32.u64 %0, t; }" : "=r"(a) : "l"(p));
    return a;
}

#define LDSM_X4(r0, r1, r2, r3, addr)                                         \
    asm volatile("ldmatrix.sync.aligned.m8n8.x4.shared.b16 {%0,%1,%2,%3}, [%4];" \
                 : "=r"(r0), "=r"(r1), "=r"(r2), "=r"(r3) : "r"(addr))

#define MMA16816(d, a, b0v, b1v)                                              \
    asm volatile("mma.sync.aligned.m16n8k16.row.col.f32.bf16.bf16.f32 "       \
                 "{%0,%1,%2,%3},{%4,%5,%6,%7},{%8,%9},{%0,%1,%2,%3};"         \
                 : "+f"((d)[0]), "+f"((d)[1]), "+f"((d)[2]), "+f"((d)[3])     \
                 : "r"((a)[0]), "r"((a)[1]), "r"((a)[2]), "r"((a)[3]),        \
                   "r"(b0v), "r"(b1v))

#define FMA2(d, a, b, c) asm("fma.rn.f32x2 %0, %1, %2, %3;" : "=l"(d) : "l"(a), "l"(b), "l"(c))
#define UNPACK2(lo, hi, v) asm("mov.b64 {%0, %1}, %2;" : "=f"(lo), "=f"(hi) : "l"(v))

#define CPA16(dst, src) asm volatile("cp.async.cg.shared.global [%0], [%1], 16;" :: "r"(dst), "l"(src) : "memory")
#define CPCOMMIT()      asm volatile("cp.async.commit_group;" ::: "memory")
#define CPWAIT3()       asm volatile("cp.async.wait_group 3;" ::: "memory")

__device__ __forceinline__ unsigned pkbf(__nv_bfloat16 a, __nv_bfloat16 b) {
    return ((unsigned)__bfloat16_as_ushort(b) << 16) | (unsigned)__bfloat16_as_ushort(a);
}

// ---------------------------------------------------------------------------
// Kernel 1: class means -> fp32 plane + bf16 hi/lo planes + bias; zero pads.
// ---------------------------------------------------------------------------
__global__ void k_mean(const float* __restrict__ mem) {
    int c = blockIdx.x, tid = threadIdx.x;
    if (c == 0 && tid == 0) { g_count = 0; g_nfix = 0; }
    if (c >= NC) {
        for (int d = tid; d < DIM; d += 256) {
            int tt = d >> 5, j = d & 31;
            g_mbf[(tt * NCP + c) * 64 + j] = 0;
            g_mbf[(tt * NCP + c) * 64 + 32 + j] = 0;
        }
        return;
    }
    float part = 0.f;
    for (int d = tid; d < DIM; d += 256) {
        float s = 0.f;
#pragma unroll
        for (int b = 0; b < BK; b++) s += mem[(size_t)(c * BK + b) * DIM + d];
        float m = s * (1.0f / BK);
        g_mmean[c * DIM + d] = m;
        __nv_bfloat16 hi = __float2bfloat16_rn(m);
        __nv_bfloat16 lo = __float2bfloat16_rn(m - __bfloat162float(hi));
        int tt = d >> 5, j = d & 31;
        g_mbf[(tt * NCP + c) * 64 + j] = __bfloat16_as_ushort(hi);
        g_mbf[(tt * NCP + c) * 64 + 32 + j] = __bfloat16_as_ushort(lo);
        part += m * m;
    }
#pragma unroll
    for (int o = 16; o; o >>= 1) part += __shfl_xor_sync(0xffffffffu, part, o);
    __shared__ float rb[8];
    if ((tid & 31) == 0) rb[tid >> 5] = part;
    __syncthreads();
    if (tid == 0) {
        float t = 0.f;
#pragma unroll
        for (int w = 0; w < 8; w++) t += rb[w];
        g_bias[c] = 0.5f * t;
    }
}

// ---------------------------------------------------------------------------
// Kernel 2: HMMA bf16-split GEMM + argmin + near-tie fixup list. (unchanged)
// ---------------------------------------------------------------------------
#define STAGE 28672
#define SMEM_GEMM (2 * STAGE)
__global__ void __launch_bounds__(256, 1)
k_gemm(const float* __restrict__ X, const int* __restrict__ labels,
       float* __restrict__ out) {
    extern __shared__ char sm[];
    const uint32_t sb = smem_u32(sm);
    const int tid = threadIdx.x, wid = tid >> 5, lane = tid & 31;
    const int i0 = blockIdx.x * BMG;
    const int mwarp = wid & 3, nwarp = wid >> 2;

    const int r = tid >> 1, h = tid & 1;
    const float* xrow = X + (size_t)(i0 + r) * DIM + h * 16;
    const uint4* mb4 = (const uint4*)g_mbf;

    float d[2][6][4];
#pragma unroll
    for (int a = 0; a < 2; a++)
#pragma unroll
        for (int b = 0; b < 6; b++)
#pragma unroll
            for (int e = 0; e < 4; e++) d[a][b][e] = 0.f;

    float4 cur0, cur1, cur2, cur3;
#define GLOAD(t)                                                    \
    {   const float4* p4 = (const float4*)(xrow + (t) * 32);        \
        cur0 = p4[0]; cur1 = p4[1]; cur2 = p4[2]; cur3 = p4[3]; }

#define GSTORE(t, buf)                                                          \
    {   float f[16];                                                            \
        *(float4*)(f + 0) = cur0; *(float4*)(f + 4) = cur1;                     \
        *(float4*)(f + 8) = cur2; *(float4*)(f + 12) = cur3;                    \
        unsigned hw[8], lw[8];                                                  \
        _Pragma("unroll") for (int j = 0; j < 8; j++) {                         \
            float x0 = f[2 * j], x1 = f[2 * j + 1];                             \
            __nv_bfloat16 h0 = __float2bfloat16_rn(x0);                         \
            __nv_bfloat16 h1 = __float2bfloat16_rn(x1);                         \
            __nv_bfloat16 l0 = __float2bfloat16_rn(x0 - __bfloat162float(h0));  \
            __nv_bfloat16 l1 = __float2bfloat16_rn(x1 - __bfloat162float(h1));  \
            hw[j] = pkbf(h0, h1); lw[j] = pkbf(l0, l1);                         \
        }                                                                       \
        char* Ab = sm + (buf) * STAGE;                                          \
        const int rx = r & 7;                                                   \
        *(uint4*)(Ab + r * 128 + 16 * ((2 * h + 0) ^ rx)) = make_uint4(hw[0], hw[1], hw[2], hw[3]); \
        *(uint4*)(Ab + r * 128 + 16 * ((2 * h + 1) ^ rx)) = make_uint4(hw[4], hw[5], hw[6], hw[7]); \
        *(uint4*)(Ab + r * 128 + 16 * ((4 + 2 * h) ^ rx)) = make_uint4(lw[0], lw[1], lw[2], lw[3]); \
        *(uint4*)(Ab + r * 128 + 16 * ((5 + 2 * h) ^ rx)) = make_uint4(lw[4], lw[5], lw[6], lw[7]); \
        char* Bb = Ab + 16384;                                                  \
        _Pragma("unroll") for (int q = 0; q < 3; q++) {                         \
            int g = tid + q * 256;                                              \
            int brow = g >> 3, bch = g & 7;                                     \
            *(uint4*)(Bb + brow * 128 + 16 * (bch ^ (brow & 7))) = mb4[(t) * 768 + g]; \
        }                                                                       \
    }

    GLOAD(0);
    GSTORE(0, 0);

    for (int t = 0; t < NT; t++) {
        const int buf = t & 1;
        if (t + 1 < NT) GLOAD(t + 1);
        __syncthreads();

        const uint32_t Abase = sb + buf * STAGE;
        const uint32_t Bbase = Abase + 16384;

        uint32_t afr[2][2][2][4];
#pragma unroll
        for (int mt = 0; mt < 2; mt++) {
            int rowA = mwarp * 32 + mt * 16 + (lane & 15);
            uint32_t rbase = Abase + rowA * 128;
            int rx = rowA & 7;
#pragma unroll
            for (int pl = 0; pl < 2; pl++)
#pragma unroll
                for (int s = 0; s < 2; s++) {
                    int ch = pl * 4 + s * 2 + (lane >> 4);
                    uint32_t ad = rbase + 16 * (ch ^ rx);
                    LDSM_X4(afr[mt][pl][s][0], afr[mt][pl][s][1],
                            afr[mt][pl][s][2], afr[mt][pl][s][3], ad);
                }
        }

#pragma unroll
        for (int pp = 0; pp < 3; pp++) {
            const int apl = (pp == 2) ? 1 : 0;
            const int bpl = (pp == 1) ? 1 : 0;
#pragma unroll
            for (int np = 0; np < 3; np++) {
                int rowB = nwarp * 48 + np * 16 + (lane & 15);
                uint32_t rbase = Bbase + rowB * 128;
                int rx = rowB & 7;
#pragma unroll
                for (int s = 0; s < 2; s++) {
                    int ch = bpl * 4 + s * 2 + (lane >> 4);
                    uint32_t bd = rbase + 16 * (ch ^ rx);
                    uint32_t b0, b1, b2, b3;
                    LDSM_X4(b0, b1, b2, b3, bd);
#pragma unroll
                    for (int mt = 0; mt < 2; mt++) {
                        MMA16816(d[mt][np * 2 + 0], afr[mt][apl][s], b0, b2);
                        MMA16816(d[mt][np * 2 + 1], afr[mt][apl][s], b1, b3);
                    }
                }
            }
        }
        __syncthreads();
        if (t + 1 < NT) GSTORE(t + 1, (t + 1) & 1);
    }
    __syncthreads();

    float* sc = (float*)sm;
#pragma unroll
    for (int mt = 0; mt < 2; mt++) {
#pragma unroll
        for (int np = 0; np < 3; np++)
#pragma unroll
            for (int hh = 0; hh < 2; hh++) {
                int row0 = mwarp * 32 + mt * 16 + (lane >> 2);
                int col0 = nwarp * 48 + np * 16 + hh * 8 + 2 * (lane & 3);
                const float* dd = d[mt][np * 2 + hh];
                if (col0 < NC) sc[row0 * 97 + col0] = g_bias[col0] - dd[0];
                if (col0 + 1 < NC) sc[row0 * 97 + col0 + 1] = g_bias[col0 + 1] - dd[1];
                if (col0 < NC) sc[(row0 + 8) * 97 + col0] = g_bias[col0] - dd[2];
                if (col0 + 1 < NC) sc[(row0 + 8) * 97 + col0 + 1] = g_bias[col0 + 1] - dd[3];
            }
    }
    __syncthreads();

    if (tid < BMG) {
        int gi = i0 + tid;
        const float* row = sc + tid * 97;
        float best = 3e38f, sec = 3e38f;
        int bc = 0;
#pragma unroll 4
        for (int cc = 0; cc < NC; cc++) {
            float v = row[cc];
            if (v < best) { sec = best; best = v; bc = cc; }
            else if (v < sec) sec = v;
        }
        out[gi] = (float)bc;
        if (sec - best < 0.02f) {
            int slot = atomicAdd(&g_nfix, 1);
            if (slot < NI) g_fix[slot] = gi;
        }
        unsigned bal = __ballot_sync(0xffffffffu, bc == labels[gi]);
        if ((tid & 31) == 0) atomicAdd(&g_count, __popc(bal));
    }
}

// ---------------------------------------------------------------------------
// Kernel 2b: exact fp32 re-check of near-tie instances. (unchanged)
// ---------------------------------------------------------------------------
__global__ void __launch_bounds__(256) k_fixup(const float* __restrict__ X,
                                               const int* __restrict__ labels,
                                               float* __restrict__ out) {
    const int tid = threadIdx.x, w = tid >> 5, lane = tid & 31;
    __shared__ float ssc[NC];
    const int nfix = g_nfix < NI ? g_nfix : NI;
    for (int idx = blockIdx.x; idx < nfix; idx += gridDim.x) {
        const int gi = g_fix[idx];
        const float4* x4 = (const float4*)(X + (size_t)gi * DIM);
        for (int c = w; c < NC; c += 8) {
            const float4* m4 = (const float4*)(g_mmean + (size_t)c * DIM);
            float s = 0.f;
#pragma unroll
            for (int k = 0; k < 16; k++) {
                float4 a = x4[k * 32 + lane];
                float4 b = m4[k * 32 + lane];
                s += a.x * b.x + a.y * b.y + a.z * b.z + a.w * b.w;
            }
#pragma unroll
            for (int o = 16; o; o >>= 1) s += __shfl_xor_sync(0xffffffffu, s, o);
            if (lane == 0) ssc[c] = g_bias[c] - s;
        }
        __syncthreads();
        if (tid == 0) {
            float best = 3e38f;
            int bc = 0;
            for (int cc = 0; cc < NC; cc++) {
                float v = ssc[cc];
                if (v < best) { best = v; bc = cc; }
            }
            int oldbc = (int)out[gi];
            if (oldbc != bc) {
                int lab = labels[gi];
                atomicAdd(&g_count, (bc == lab) - (oldbc == lab));
                out[gi] = (float)bc;
            }
        }
        __syncthreads();
    }
}

// ---------------------------------------------------------------------------
// Kernel 3: sequential per-class update. cp.async 4-deep smem ring for X rows
// (zero register cost, per-thread wait -> no extra barriers). Two barriers per
// step: warp-reduce + warp0 decision. Bank in registers (f32x2).
// ---------------------------------------------------------------------------
__global__ void __launch_bounds__(256, 1)
k_update(const float* __restrict__ X, const int* __restrict__ labels,
         const float* __restrict__ mem, const int* __restrict__ mpos,
         float* __restrict__ out) {
    const int c = blockIdx.x, tid = threadIdx.x;
    const int w = tid >> 5, lane = tid & 31;
    if (c == 0 && tid == 0) out[NI] = (float)g_count * (1.0f / NI);

    __shared__ float s_x[4][DIM];       // 32KB cp.async ring
    __shared__ int   s_list[1024];
    __shared__ int   s_cnt;
    __shared__ int   s_wcnt[8];
    __shared__ float s_part[8][12];
    __shared__ float s_bn[BK];
    __shared__ int   s_slot;

    // ---- ordered index list for class c ----
    const int SEG = NI / 8;
    const int base = w * SEG;
    const int4* lab4 = (const int4*)labels;
    int cnt = 0;
    for (int it = 0; it < SEG / 128; it++) {
        int4 v = lab4[(base >> 2) + it * 32 + lane];
        cnt += (v.x == c) + (v.y == c) + (v.z == c) + (v.w == c);
    }
#pragma unroll
    for (int o = 16; o; o >>= 1) cnt += __shfl_xor_sync(0xffffffffu, cnt, o);
    if (lane == 0) s_wcnt[w] = cnt;
    __syncthreads();
    if (tid == 0) {
        int t = 0;
        for (int ww = 0; ww < 8; ww++) { int v = s_wcnt[ww]; s_wcnt[ww] = t; t += v; }
        s_cnt = t;
    }
    __syncthreads();
    int off = s_wcnt[w];
    for (int it = 0; it < SEG / 128; it++) {
        int gidx = base + it * 128 + lane * 4;
        int4 v = lab4[gidx >> 2];
        int m0 = (v.x == c), m1 = (v.y == c), m2 = (v.z == c), m3 = (v.w == c);
        int nm = m0 + m1 + m2 + m3;
        int x = nm;
#pragma unroll
        for (int o = 1; o < 32; o <<= 1) {
            int y = __shfl_up_sync(0xffffffffu, x, o);
            if (lane >= o) x += y;
        }
        int p2 = off + x - nm;
        if (m0) { s_list[p2 < 1024 ? p2 : 1023] = gidx + 0; p2++; }
        if (m1) { s_list[p2 < 1024 ? p2 : 1023] = gidx + 1; p2++; }
        if (m2) { s_list[p2 < 1024 ? p2 : 1023] = gidx + 2; p2++; }
        if (m3) { s_list[p2 < 1024 ? p2 : 1023] = gidx + 3; p2++; }
        off += __shfl_sync(0xffffffffu, x, 31);
    }
    __syncthreads();

    const int n = s_cnt < 1024 ? s_cnt : 1024;

    // ---- warm the cp.async ring with rows 0..3 (per-thread 2x16B) ----
    const uint32_t ringA = smem_u32(s_x) + tid * 16;   // dims [4t,4t+4)
    const uint32_t ringB = ringA + 4096;               // dims [1024+4t, +4)
#pragma unroll
    for (int dpt = 0; dpt < 4; dpt++) {
        if (dpt < n) {
            const float* src = X + (size_t)s_list[dpt] * DIM + tid * 4;
            CPA16(ringA + dpt * 8192, src);
            CPA16(ringB + dpt * 8192, src + 1024);
        }
        CPCOMMIT();
    }

    // ---- bank into registers (f32x2 pairs); |b_j|^2 -> s_bn ----
    const ulonglong2* memU = (const ulonglong2*)mem + (size_t)c * BK * (DIM / 4);
    ulonglong2 br[BK][2];
    float part[11];
#pragma unroll
    for (int j = 0; j < BK; j++) {
        br[j][0] = memU[j * 512 + tid];
        br[j][1] = memU[j * 512 + 256 + tid];
        unsigned long long pa = 0ull;
        FMA2(pa, br[j][0].x, br[j][0].x, pa);
        FMA2(pa, br[j][0].y, br[j][0].y, pa);
        FMA2(pa, br[j][1].x, br[j][1].x, pa);
        FMA2(pa, br[j][1].y, br[j][1].y, pa);
        float lo, hi; UNPACK2(lo, hi, pa);
        part[j] = lo + hi;
    }
#pragma unroll
    for (int j = 0; j < BK; j++) {
        float v = part[j];
#pragma unroll
        for (int o = 16; o; o >>= 1) v += __shfl_xor_sync(0xffffffffu, v, o);
        part[j] = v;
    }
    if (lane == 0) {
#pragma unroll
        for (int j = 0; j < BK; j++) s_part[w][j] = part[j];
    }
    __syncthreads();
    if (tid < BK) {
        float t = 0.f;
#pragma unroll
        for (int ww = 0; ww < 8; ww++) t += s_part[ww][tid];
        s_bn[tid] = t;
    }
    __syncthreads();

    // ---- sequential scan ----
    int p = mpos[c];
    for (int s = 0; s < n; s++) {
        CPWAIT3();                       // row s resident in ring slot s&3
        const float* xr = s_x[s & 3];
        float4 xa = *(const float4*)(xr + tid * 4);
        float4 xb = *(const float4*)(xr + 1024 + tid * 4);
        // issue row s+4 into the slot just consumed
        if (s + 4 < n) {
            const float* src = X + (size_t)s_list[s + 4] * DIM + tid * 4;
            CPA16(ringA + (s & 3) * 8192, src);
            CPA16(ringB + (s & 3) * 8192, src + 1024);
        }
        CPCOMMIT();

        ulonglong2 X0 = *(ulonglong2*)&xa;
        ulonglong2 X1 = *(ulonglong2*)&xb;
        float p10;
#pragma unroll
        for (int j = 0; j < BK; j++) {
            unsigned long long pa = 0ull;
            FMA2(pa, br[j][0].x, X0.x, pa);
            FMA2(pa, br[j][0].y, X0.y, pa);
            FMA2(pa, br[j][1].x, X1.x, pa);
            FMA2(pa, br[j][1].y, X1.y, pa);
            float lo, hi; UNPACK2(lo, hi, pa);
            part[j] = lo + hi;
        }
        {
            unsigned long long pa = 0ull;
            FMA2(pa, X0.x, X0.x, pa); FMA2(pa, X0.y, X0.y, pa);
            FMA2(pa, X1.x, X1.x, pa); FMA2(pa, X1.y, X1.y, pa);
            float lo, hi; UNPACK2(lo, hi, pa);
            p10 = lo + hi;
        }
#pragma unroll
        for (int j = 0; j < BK; j++) {
            float v = part[j];
#pragma unroll
            for (int o = 16; o; o >>= 1) v += __shfl_xor_sync(0xffffffffu, v, o);
            part[j] = v;
        }
#pragma unroll
        for (int o = 16; o; o >>= 1) p10 += __shfl_xor_sync(0xffffffffu, p10, o);
        if (lane == 0) {
#pragma unroll
            for (int j = 0; j < BK; j++) s_part[w][j] = part[j];
            s_part[w][10] = p10;
        }
        __syncthreads();

        if (w == 0) {
            float tot = 0.f;
            if (lane < 11) {
#pragma unroll
                for (int ww = 0; ww < 8; ww++) tot += s_part[ww][lane];
            }
            float xx = __shfl_sync(0xffffffffu, tot, 10);
            float dd = -CUDART_INF_F;
            if (lane < BK) dd = fmaf(-2.f, tot, s_bn[lane]);
            float mx = dd;
#pragma unroll
            for (int o = 8; o; o >>= 1) mx = fmaxf(mx, __shfl_xor_sync(0xffffffffu, mx, o));
            unsigned bal = __ballot_sync(0xffffffffu, dd == mx) & 0x3FFu;
            int slot = (p < BK) ? p : (__ffs(bal) - 1);
            if (lane == 0) {
                s_slot = slot;
                s_bn[slot] = xx;
            }
        }
        __syncthreads();

        const int slot = s_slot;
#pragma unroll
        for (int j = 0; j < BK; j++) {
            bool hh = (slot == j);
            br[j][0].x = hh ? X0.x : br[j][0].x;
            br[j][0].y = hh ? X0.y : br[j][0].y;
            br[j][1].x = hh ? X1.x : br[j][1].x;
            br[j][1].y = hh ? X1.y : br[j][1].y;
        }
        if (p < BK) p++;
    }

    // ---- epilogue (out+16385 only 4B-aligned -> scalar stores) ----
    float* om = out + (NI + 1) + (size_t)c * BK * DIM;
#pragma unroll
    for (int j = 0; j < BK; j++) {
        float f0, f1, f2, f3;
        UNPACK2(f0, f1, br[j][0].x); UNPACK2(f2, f3, br[j][0].y);
        int d0 = j * DIM + tid * 4;
        om[d0 + 0] = f0; om[d0 + 1] = f1; om[d0 + 2] = f2; om[d0 + 3] = f3;
        UNPACK2(f0, f1, br[j][1].x); UNPACK2(f2, f3, br[j][1].y);
        int d1 = j * DIM + 1024 + tid * 4;
        om[d1 + 0] = f0; om[d1 + 1] = f1; om[d1 + 2] = f2; om[d1 + 3] = f3;
    }
    if (tid == 0) out[(NI + 1) + (size_t)NC * BK * DIM + c] = (float)p;
}

// ---------------------------------------------------------------------------
extern "C" void kernel_launch(void* const* d_in, const int* in_sizes, int n_in,
                              void* d_out, int out_size) {
    const float* X      = (const float*)d_in[0];
    const int*   labels = (const int*)d_in[1];
    const float* mem    = (const float*)d_in[2];
    const int*   mpos   = (const int*)d_in[3];
    float* out = (float*)d_out;

    static bool init = false;
    if (!init) {
        init = true;
        cudaFuncSetAttribute(k_gemm, cudaFuncAttributeMaxDynamicSharedMemorySize, SMEM_GEMM);
    }

    k_mean<<<NCP, 256>>>(mem);
    k_gemm<<<NI / BMG, 256, SMEM_GEMM>>>(X, labels, out);
    k_fixup<<<296, 256>>>(X, labels, out);
    k_update<<<NC, 256>>>(X, labels, mem, mpos, out);
}

// round 6
// speedup vs baseline: 1.5507x; 1.0335x over previous
#include <cuda_runtime.h>
#include <cuda_bf16.h>
#include <math_constants.h>
#include <cstdint>

#define NC   81
#define NCP  96
#define BK   10
#define DIM  2048
#define NI   16384
#define NT   64          /* k-tiles of 32 fp32 dims */
#define BMG  128         /* gemm instances per block */

__device__ int   g_count;
__device__ int   g_nfix;
__device__ int   g_fix[NI];
__device__ float g_bias[NCP];
__device__ float g_mmean[NC * DIM];
// [tile][class][hi(32)|lo(32)] bf16 => 128B per class-row per tile
__device__ __align__(16) unsigned short g_mbf[NT * NCP * 64];

__device__ __forceinline__ uint32_t smem_u32(const void* p) {
    uint32_t a;
    asm("{ .reg .u64 t; cvta.to.shared.u64 t, %1; cvt.u32.u64 %0, t; }" : "=r"(a) : "l"(p));
    return a;
}

#define LDSM_X4(r0, r1, r2, r3, addr)                                         \
    asm volatile("ldmatrix.sync.aligned.m8n8.x4.shared.b16 {%0,%1,%2,%3}, [%4];" \
                 : "=r"(r0), "=r"(r1), "=r"(r2), "=r"(r3) : "r"(addr))

#define MMA16816(d, a, b0v, b1v)                                              \
    asm volatile("mma.sync.aligned.m16n8k16.row.col.f32.bf16.bf16.f32 "       \
                 "{%0,%1,%2,%3},{%4,%5,%6,%7},{%8,%9},{%0,%1,%2,%3};"         \
                 : "+f"((d)[0]), "+f"((d)[1]), "+f"((d)[2]), "+f"((d)[3])     \
                 : "r"((a)[0]), "r"((a)[1]), "r"((a)[2]), "r"((a)[3]),        \
                   "r"(b0v), "r"(b1v))

#define FMA2(d, a, b, c) asm("fma.rn.f32x2 %0, %1, %2, %3;" : "=l"(d) : "l"(a), "l"(b), "l"(c))
#define UNPACK2(lo, hi, v) asm("mov.b64 {%0, %1}, %2;" : "=f"(lo), "=f"(hi) : "l"(v))

#define CPA16(dst, src) asm volatile("cp.async.cg.shared.global [%0], [%1], 16;" :: "r"(dst), "l"(src) : "memory")
#define CPCOMMIT()      asm volatile("cp.async.commit_group;" ::: "memory")
#define CPWAIT3()       asm volatile("cp.async.wait_group 3;" ::: "memory")

__device__ __forceinline__ unsigned pkbf(__nv_bfloat16 a, __nv_bfloat16 b) {
    return ((unsigned)__bfloat16_as_ushort(b) << 16) | (unsigned)__bfloat16_as_ushort(a);
}

// ---------------------------------------------------------------------------
// Kernel 1: class means -> fp32 plane + bf16 hi/lo planes + bias; zero pads.
// ---------------------------------------------------------------------------
__global__ void k_mean(const float* __restrict__ mem) {
    int c = blockIdx.x, tid = threadIdx.x;
    if (c == 0 && tid == 0) { g_count = 0; g_nfix = 0; }
    if (c >= NC) {
        for (int d = tid; d < DIM; d += 256) {
            int tt = d >> 5, j = d & 31;
            g_mbf[(tt * NCP + c) * 64 + j] = 0;
            g_mbf[(tt * NCP + c) * 64 + 32 + j] = 0;
        }
        return;
    }
    float part = 0.f;
    for (int d = tid; d < DIM; d += 256) {
        float s = 0.f;
#pragma unroll
        for (int b = 0; b < BK; b++) s += mem[(size_t)(c * BK + b) * DIM + d];
        float m = s * (1.0f / BK);
        g_mmean[c * DIM + d] = m;
        __nv_bfloat16 hi = __float2bfloat16_rn(m);
        __nv_bfloat16 lo = __float2bfloat16_rn(m - __bfloat162float(hi));
        int tt = d >> 5, j = d & 31;
        g_mbf[(tt * NCP + c) * 64 + j] = __bfloat16_as_ushort(hi);
        g_mbf[(tt * NCP + c) * 64 + 32 + j] = __bfloat16_as_ushort(lo);
        part += m * m;
    }
#pragma unroll
    for (int o = 16; o; o >>= 1) part += __shfl_xor_sync(0xffffffffu, part, o);
    __shared__ float rb[8];
    if ((tid & 31) == 0) rb[tid >> 5] = part;
    __syncthreads();
    if (tid == 0) {
        float t = 0.f;
#pragma unroll
        for (int w = 0; w < 8; w++) t += rb[w];
        g_bias[c] = 0.5f * t;
    }
}

// ---------------------------------------------------------------------------
// Kernel 2: HMMA bf16-split GEMM + argmin + near-tie fixup list. (unchanged)
// ---------------------------------------------------------------------------
#define STAGE 28672
#define SMEM_GEMM (2 * STAGE)
__global__ void __launch_bounds__(256, 1)
k_gemm(const float* __restrict__ X, const int* __restrict__ labels,
       float* __restrict__ out) {
    extern __shared__ char sm[];
    const uint32_t sb = smem_u32(sm);
    const int tid = threadIdx.x, wid = tid >> 5, lane = tid & 31;
    const int i0 = blockIdx.x * BMG;
    const int mwarp = wid & 3, nwarp = wid >> 2;

    const int r = tid >> 1, h = tid & 1;
    const float* xrow = X + (size_t)(i0 + r) * DIM + h * 16;
    const uint4* mb4 = (const uint4*)g_mbf;

    float d[2][6][4];
#pragma unroll
    for (int a = 0; a < 2; a++)
#pragma unroll
        for (int b = 0; b < 6; b++)
#pragma unroll
            for (int e = 0; e < 4; e++) d[a][b][e] = 0.f;

    float4 cur0, cur1, cur2, cur3;
#define GLOAD(t)                                                    \
    {   const float4* p4 = (const float4*)(xrow + (t) * 32);        \
        cur0 = p4[0]; cur1 = p4[1]; cur2 = p4[2]; cur3 = p4[3]; }

#define GSTORE(t, buf)                                                          \
    {   float f[16];                                                            \
        *(float4*)(f + 0) = cur0; *(float4*)(f + 4) = cur1;                     \
        *(float4*)(f + 8) = cur2; *(float4*)(f + 12) = cur3;                    \
        unsigned hw[8], lw[8];                                                  \
        _Pragma("unroll") for (int j = 0; j < 8; j++) {                         \
            float x0 = f[2 * j], x1 = f[2 * j + 1];                             \
            __nv_bfloat16 h0 = __float2bfloat16_rn(x0);                         \
            __nv_bfloat16 h1 = __float2bfloat16_rn(x1);                         \
            __nv_bfloat16 l0 = __float2bfloat16_rn(x0 - __bfloat162float(h0));  \
            __nv_bfloat16 l1 = __float2bfloat16_rn(x1 - __bfloat162float(h1));  \
            hw[j] = pkbf(h0, h1); lw[j] = pkbf(l0, l1);                         \
        }                                                                       \
        char* Ab = sm + (buf) * STAGE;                                          \
        const int rx = r & 7;                                                   \
        *(uint4*)(Ab + r * 128 + 16 * ((2 * h + 0) ^ rx)) = make_uint4(hw[0], hw[1], hw[2], hw[3]); \
        *(uint4*)(Ab + r * 128 + 16 * ((2 * h + 1) ^ rx)) = make_uint4(hw[4], hw[5], hw[6], hw[7]); \
        *(uint4*)(Ab + r * 128 + 16 * ((4 + 2 * h) ^ rx)) = make_uint4(lw[0], lw[1], lw[2], lw[3]); \
        *(uint4*)(Ab + r * 128 + 16 * ((5 + 2 * h) ^ rx)) = make_uint4(lw[4], lw[5], lw[6], lw[7]); \
        char* Bb = Ab + 16384;                                                  \
        _Pragma("unroll") for (int q = 0; q < 3; q++) {                         \
            int g = tid + q * 256;                                              \
            int brow = g >> 3, bch = g & 7;                                     \
            *(uint4*)(Bb + brow * 128 + 16 * (bch ^ (brow & 7))) = mb4[(t) * 768 + g]; \
        }                                                                       \
    }

    GLOAD(0);
    GSTORE(0, 0);

    for (int t = 0; t < NT; t++) {
        const int buf = t & 1;
        if (t + 1 < NT) GLOAD(t + 1);
        __syncthreads();

        const uint32_t Abase = sb + buf * STAGE;
        const uint32_t Bbase = Abase + 16384;

        uint32_t afr[2][2][2][4];
#pragma unroll
        for (int mt = 0; mt < 2; mt++) {
            int rowA = mwarp * 32 + mt * 16 + (lane & 15);
            uint32_t rbase = Abase + rowA * 128;
            int rx = rowA & 7;
#pragma unroll
            for (int pl = 0; pl < 2; pl++)
#pragma unroll
                for (int s = 0; s < 2; s++) {
                    int ch = pl * 4 + s * 2 + (lane >> 4);
                    uint32_t ad = rbase + 16 * (ch ^ rx);
                    LDSM_X4(afr[mt][pl][s][0], afr[mt][pl][s][1],
                            afr[mt][pl][s][2], afr[mt][pl][s][3], ad);
                }
        }

#pragma unroll
        for (int pp = 0; pp < 3; pp++) {
            const int apl = (pp == 2) ? 1 : 0;
            const int bpl = (pp == 1) ? 1 : 0;
#pragma unroll
            for (int np = 0; np < 3; np++) {
                int rowB = nwarp * 48 + np * 16 + (lane & 15);
                uint32_t rbase = Bbase + rowB * 128;
                int rx = rowB & 7;
#pragma unroll
                for (int s = 0; s < 2; s++) {
                    int ch = bpl * 4 + s * 2 + (lane >> 4);
                    uint32_t bd = rbase + 16 * (ch ^ rx);
                    uint32_t b0, b1, b2, b3;
                    LDSM_X4(b0, b1, b2, b3, bd);
#pragma unroll
                    for (int mt = 0; mt < 2; mt++) {
                        MMA16816(d[mt][np * 2 + 0], afr[mt][apl][s], b0, b2);
                        MMA16816(d[mt][np * 2 + 1], afr[mt][apl][s], b1, b3);
                    }
                }
            }
        }
        __syncthreads();
        if (t + 1 < NT) GSTORE(t + 1, (t + 1) & 1);
    }
    __syncthreads();

    float* sc = (float*)sm;
#pragma unroll
    for (int mt = 0; mt < 2; mt++) {
#pragma unroll
        for (int np = 0; np < 3; np++)
#pragma unroll
            for (int hh = 0; hh < 2; hh++) {
                int row0 = mwarp * 32 + mt * 16 + (lane >> 2);
                int col0 = nwarp * 48 + np * 16 + hh * 8 + 2 * (lane & 3);
                const float* dd = d[mt][np * 2 + hh];
                if (col0 < NC) sc[row0 * 97 + col0] = g_bias[col0] - dd[0];
                if (col0 + 1 < NC) sc[row0 * 97 + col0 + 1] = g_bias[col0 + 1] - dd[1];
                if (col0 < NC) sc[(row0 + 8) * 97 + col0] = g_bias[col0] - dd[2];
                if (col0 + 1 < NC) sc[(row0 + 8) * 97 + col0 + 1] = g_bias[col0 + 1] - dd[3];
            }
    }
    __syncthreads();

    if (tid < BMG) {
        int gi = i0 + tid;
        const float* row = sc + tid * 97;
        float best = 3e38f, sec = 3e38f;
        int bc = 0;
#pragma unroll 4
        for (int cc = 0; cc < NC; cc++) {
            float v = row[cc];
            if (v < best) { sec = best; best = v; bc = cc; }
            else if (v < sec) sec = v;
        }
        out[gi] = (float)bc;
        if (sec - best < 0.02f) {
            int slot = atomicAdd(&g_nfix, 1);
            if (slot < NI) g_fix[slot] = gi;
        }
        unsigned bal = __ballot_sync(0xffffffffu, bc == labels[gi]);
        if ((tid & 31) == 0) atomicAdd(&g_count, __popc(bal));
    }
}

// ---------------------------------------------------------------------------
// Kernel 2b: exact fp32 re-check of near-tie instances. (unchanged)
// ---------------------------------------------------------------------------
__global__ void __launch_bounds__(256) k_fixup(const float* __restrict__ X,
                                               const int* __restrict__ labels,
                                               float* __restrict__ out) {
    const int tid = threadIdx.x, w = tid >> 5, lane = tid & 31;
    __shared__ float ssc[NC];
    const int nfix = g_nfix < NI ? g_nfix : NI;
    for (int idx = blockIdx.x; idx < nfix; idx += gridDim.x) {
        const int gi = g_fix[idx];
        const float4* x4 = (const float4*)(X + (size_t)gi * DIM);
        for (int c = w; c < NC; c += 8) {
            const float4* m4 = (const float4*)(g_mmean + (size_t)c * DIM);
            float s = 0.f;
#pragma unroll
            for (int k = 0; k < 16; k++) {
                float4 a = x4[k * 32 + lane];
                float4 b = m4[k * 32 + lane];
                s += a.x * b.x + a.y * b.y + a.z * b.z + a.w * b.w;
            }
#pragma unroll
            for (int o = 16; o; o >>= 1) s += __shfl_xor_sync(0xffffffffu, s, o);
            if (lane == 0) ssc[c] = g_bias[c] - s;
        }
        __syncthreads();
        if (tid == 0) {
            float best = 3e38f;
            int bc = 0;
            for (int cc = 0; cc < NC; cc++) {
                float v = ssc[cc];
                if (v < best) { best = v; bc = cc; }
            }
            int oldbc = (int)out[gi];
            if (oldbc != bc) {
                int lab = labels[gi];
                atomicAdd(&g_count, (bc == lab) - (oldbc == lab));
                out[gi] = (float)bc;
            }
        }
        __syncthreads();
    }
}

// ---------------------------------------------------------------------------
// Kernel 3: sequential per-class update. cp.async 4-deep smem ring + smem
// transpose-reduction (no 55-shfl trees): stage A STS partials -> BAR ->
// stage B one warp per slot row (2 LDS.128 + one 5-shfl tree) -> BAR ->
// redundant decision on all threads. Bank + bn in registers.
// ---------------------------------------------------------------------------
__global__ void __launch_bounds__(256, 1)
k_update(const float* __restrict__ X, const int* __restrict__ labels,
         const float* __restrict__ mem, const int* __restrict__ mpos,
         float* __restrict__ out) {
    const int c = blockIdx.x, tid = threadIdx.x;
    const int w = tid >> 5, lane = tid & 31;
    if (c == 0 && tid == 0) out[NI] = (float)g_count * (1.0f / NI);

    __shared__ float s_x[4][DIM];            // 32KB cp.async ring
    __shared__ float s_p[11][256];           // 11KB partials (transpose layout)
    __shared__ int   s_list[1024];
    __shared__ int   s_cnt;
    __shared__ int   s_wcnt[8];
    __shared__ __align__(16) float s_red[12];

    // ---- ordered index list for class c ----
    const int SEG = NI / 8;
    const int base = w * SEG;
    const int4* lab4 = (const int4*)labels;
    int cnt = 0;
    for (int it = 0; it < SEG / 128; it++) {
        int4 v = lab4[(base >> 2) + it * 32 + lane];
        cnt += (v.x == c) + (v.y == c) + (v.z == c) + (v.w == c);
    }
#pragma unroll
    for (int o = 16; o; o >>= 1) cnt += __shfl_xor_sync(0xffffffffu, cnt, o);
    if (lane == 0) s_wcnt[w] = cnt;
    __syncthreads();
    if (tid == 0) {
        int t = 0;
        for (int ww = 0; ww < 8; ww++) { int v = s_wcnt[ww]; s_wcnt[ww] = t; t += v; }
        s_cnt = t;
    }
    __syncthreads();
    int off = s_wcnt[w];
    for (int it = 0; it < SEG / 128; it++) {
        int gidx = base + it * 128 + lane * 4;
        int4 v = lab4[gidx >> 2];
        int m0 = (v.x == c), m1 = (v.y == c), m2 = (v.z == c), m3 = (v.w == c);
        int nm = m0 + m1 + m2 + m3;
        int x = nm;
#pragma unroll
        for (int o = 1; o < 32; o <<= 1) {
            int y = __shfl_up_sync(0xffffffffu, x, o);
            if (lane >= o) x += y;
        }
        int p2 = off + x - nm;
        if (m0) { s_list[p2 < 1024 ? p2 : 1023] = gidx + 0; p2++; }
        if (m1) { s_list[p2 < 1024 ? p2 : 1023] = gidx + 1; p2++; }
        if (m2) { s_list[p2 < 1024 ? p2 : 1023] = gidx + 2; p2++; }
        if (m3) { s_list[p2 < 1024 ? p2 : 1023] = gidx + 3; p2++; }
        off += __shfl_sync(0xffffffffu, x, 31);
    }
    __syncthreads();

    const int n = s_cnt < 1024 ? s_cnt : 1024;

    // ---- warm the cp.async ring with rows 0..3 (per-thread 2x16B) ----
    const uint32_t ringA = smem_u32(s_x) + tid * 16;   // dims [4t,4t+4)
    const uint32_t ringB = ringA + 4096;               // dims [1024+4t, +4)
#pragma unroll
    for (int dpt = 0; dpt < 4; dpt++) {
        if (dpt < n) {
            const float* src = X + (size_t)s_list[dpt] * DIM + tid * 4;
            CPA16(ringA + dpt * 8192, src);
            CPA16(ringB + dpt * 8192, src + 1024);
        }
        CPCOMMIT();
    }

    // ---- bank into registers (f32x2 pairs); |b_j|^2 via smem reduction ----
    const ulonglong2* memU = (const ulonglong2*)mem + (size_t)c * BK * (DIM / 4);
    ulonglong2 br[BK][2];
#pragma unroll
    for (int j = 0; j < BK; j++) {
        br[j][0] = memU[j * 512 + tid];
        br[j][1] = memU[j * 512 + 256 + tid];
        unsigned long long pa = 0ull;
        FMA2(pa, br[j][0].x, br[j][0].x, pa);
        FMA2(pa, br[j][0].y, br[j][0].y, pa);
        FMA2(pa, br[j][1].x, br[j][1].x, pa);
        FMA2(pa, br[j][1].y, br[j][1].y, pa);
        float lo, hi; UNPACK2(lo, hi, pa);
        s_p[j][tid] = lo + hi;
    }
    s_p[10][tid] = 0.f;
    __syncthreads();

#define STAGE_B()                                                             \
    {                                                                         \
        {                                                                     \
            const float4* rp = (const float4*)s_p[w];                         \
            float4 a0 = rp[lane], a1 = rp[lane + 32];                         \
            float v = (a0.x + a0.y) + (a0.z + a0.w) +                         \
                      (a1.x + a1.y) + (a1.z + a1.w);                          \
            _Pragma("unroll") for (int o = 16; o; o >>= 1)                    \
                v += __shfl_xor_sync(0xffffffffu, v, o);                      \
            if (lane == 0) s_red[w] = v;                                      \
        }                                                                     \
        if (w < 3) {                                                          \
            const float4* rp = (const float4*)s_p[8 + w];                     \
            float4 a0 = rp[lane], a1 = rp[lane + 32];                         \
            float v = (a0.x + a0.y) + (a0.z + a0.w) +                         \
                      (a1.x + a1.y) + (a1.z + a1.w);                          \
            _Pragma("unroll") for (int o = 16; o; o >>= 1)                    \
                v += __shfl_xor_sync(0xffffffffu, v, o);                      \
            if (lane == 0) s_red[8 + w] = v;                                  \
        }                                                                     \
    }

    STAGE_B();
    __syncthreads();

    float bn[BK];
    {
        float4 ra = *(const float4*)s_red;
        float4 rb2 = *(const float4*)(s_red + 4);
        float4 rc = *(const float4*)(s_red + 8);
        bn[0] = ra.x; bn[1] = ra.y; bn[2] = ra.z; bn[3] = ra.w;
        bn[4] = rb2.x; bn[5] = rb2.y; bn[6] = rb2.z; bn[7] = rb2.w;
        bn[8] = rc.x; bn[9] = rc.y;
    }
    __syncthreads();   // s_red consumed before loop writes it again

    // ---- sequential scan ----
    int p = mpos[c];
    for (int s = 0; s < n; s++) {
        CPWAIT3();                       // row s resident in ring slot s&3
        const float* xr = s_x[s & 3];
        float4 xa = *(const float4*)(xr + tid * 4);
        float4 xb = *(const float4*)(xr + 1024 + tid * 4);
        if (s + 4 < n) {
            const float* src = X + (size_t)s_list[s + 4] * DIM + tid * 4;
            CPA16(ringA + (s & 3) * 8192, src);
            CPA16(ringB + (s & 3) * 8192, src + 1024);
        }
        CPCOMMIT();

        ulonglong2 X0 = *(ulonglong2*)&xa;
        ulonglong2 X1 = *(ulonglong2*)&xb;
#pragma unroll
        for (int j = 0; j < BK; j++) {
            unsigned long long pa = 0ull;
            FMA2(pa, br[j][0].x, X0.x, pa);
            FMA2(pa, br[j][0].y, X0.y, pa);
            FMA2(pa, br[j][1].x, X1.x, pa);
            FMA2(pa, br[j][1].y, X1.y, pa);
            float lo, hi; UNPACK2(lo, hi, pa);
            s_p[j][tid] = lo + hi;
        }
        {
            unsigned long long pa = 0ull;
            FMA2(pa, X0.x, X0.x, pa); FMA2(pa, X0.y, X0.y, pa);
            FMA2(pa, X1.x, X1.x, pa); FMA2(pa, X1.y, X1.y, pa);
            float lo, hi; UNPACK2(lo, hi, pa);
            s_p[10][tid] = lo + hi;
        }
        __syncthreads();

        STAGE_B();
        __syncthreads();

        // redundant decision on every thread (broadcast reads, no 3rd barrier)
        float tot[11], xx;
        {
            float4 ra = *(const float4*)s_red;
            float4 rb2 = *(const float4*)(s_red + 4);
            float4 rc = *(const float4*)(s_red + 8);
            tot[0] = ra.x; tot[1] = ra.y; tot[2] = ra.z; tot[3] = ra.w;
            tot[4] = rb2.x; tot[5] = rb2.y; tot[6] = rb2.z; tot[7] = rb2.w;
            tot[8] = rc.x; tot[9] = rc.y; xx = rc.z;
        }
        int slot;
        if (p < BK) {
            slot = p;
        } else {
            float dd[BK];
#pragma unroll
            for (int j = 0; j < BK; j++) dd[j] = fmaf(-2.f, tot[j], bn[j]);
            float mx = dd[0];
#pragma unroll
            for (int j = 1; j < BK; j++) mx = fmaxf(mx, dd[j]);
            slot = BK - 1;
#pragma unroll
            for (int j = BK - 1; j >= 0; j--) slot = (dd[j] == mx) ? j : slot;
        }
#pragma unroll
        for (int j = 0; j < BK; j++) {
            bool hh = (slot == j);
            br[j][0].x = hh ? X0.x : br[j][0].x;
            br[j][0].y = hh ? X0.y : br[j][0].y;
            br[j][1].x = hh ? X1.x : br[j][1].x;
            br[j][1].y = hh ? X1.y : br[j][1].y;
            bn[j] = hh ? xx : bn[j];
        }
        if (p < BK) p++;
    }

    // ---- epilogue (out+16385 only 4B-aligned -> scalar stores) ----
    float* om = out + (NI + 1) + (size_t)c * BK * DIM;
#pragma unroll
    for (int j = 0; j < BK; j++) {
        float f0, f1, f2, f3;
        UNPACK2(f0, f1, br[j][0].x); UNPACK2(f2, f3, br[j][0].y);
        int d0 = j * DIM + tid * 4;
        om[d0 + 0] = f0; om[d0 + 1] = f1; om[d0 + 2] = f2; om[d0 + 3] = f3;
        UNPACK2(f0, f1, br[j][1].x); UNPACK2(f2, f3, br[j][1].y);
        int d1 = j * DIM + 1024 + tid * 4;
        om[d1 + 0] = f0; om[d1 + 1] = f1; om[d1 + 2] = f2; om[d1 + 3] = f3;
    }
    if (tid == 0) out[(NI + 1) + (size_t)NC * BK * DIM + c] = (float)p;
}

// ---------------------------------------------------------------------------
extern "C" void kernel_launch(void* const* d_in, const int* in_sizes, int n_in,
                              void* d_out, int out_size) {
    const float* X      = (const float*)d_in[0];
    const int*   labels = (const int*)d_in[1];
    const float* mem    = (const float*)d_in[2];
    const int*   mpos   = (const int*)d_in[3];
    float* out = (float*)d_out;

    static bool init = false;
    if (!init) {
        init = true;
        cudaFuncSetAttribute(k_gemm, cudaFuncAttributeMaxDynamicSharedMemorySize, SMEM_GEMM);
    }

    k_mean<<<NCP, 256>>>(mem);
    k_gemm<<<NI / BMG, 256, SMEM_GEMM>>>(X, labels, out);
    k_fixup<<<296, 256>>>(X, labels, out);
    k_update<<<NC, 256>>>(X, labels, mem, mpos, out);
}